// round 3
// baseline (speedup 1.0000x reference)
#include <cuda_runtime.h>
#include <cuda_bf16.h>
#include <math.h>

#define BATCH 8
#define CC 64
#define NN 110592               // 48*48*48
#define CHUNK 2048
#define SPLITS 54               // 54*2048 = 110592
#define TILE_N 32
#define KA_PAD 68               // 32 rows of [n][c], padded to 68 floats (272B, 16B-aligned)
#define TN 64                   // n-tile for output kernel

// Scratch (device globals; no allocation allowed)
__device__ float g_Gpart[SPLITS * BATCH * CC * CC];   // ~7.1 MB
__device__ float g_aff[BATCH * CC * CC];              // 128 KB

// ---------------------------------------------------------------------------
// Kernel A: partial Gram matrices. G_s[c][d] = sum_{n in chunk s} K[c,n]K[d,n]
// grid = (SPLITS, BATCH), block = 128 (tx=tid&7 -> 8 d-groups, ty=tid>>3 -> 16 c-groups)
// Each thread accumulates a 4(c) x 8(d) register tile.
// ---------------------------------------------------------------------------
__global__ __launch_bounds__(128) void gram_kernel(const float* __restrict__ x) {
    const int s = blockIdx.x;
    const int b = blockIdx.y;
    const float* __restrict__ xb = x + (size_t)b * CC * NN;

    __shared__ float Ks[TILE_N * KA_PAD];   // [n_local][c] transposed tile

    const int tid = threadIdx.x;
    const int tx = tid & 7;
    const int ty = tid >> 3;
    const int c0 = ty * 4;
    const int d0 = tx * 8;

    float acc[4][8];
#pragma unroll
    for (int i = 0; i < 4; i++)
#pragma unroll
        for (int j = 0; j < 8; j++) acc[i][j] = 0.0f;

    const int nbase = s * CHUNK;

    for (int t0 = 0; t0 < CHUNK; t0 += TILE_N) {
        // Load 64 rows x 32 n = 512 float4, coalesced from gmem, transposed into smem
#pragma unroll
        for (int r = 0; r < 4; r++) {
            int fidx = tid + r * 128;
            int c  = fidx >> 3;           // 0..63
            int jj = (fidx & 7) * 4;      // 0..28
            float4 v = *(const float4*)&xb[(size_t)c * NN + nbase + t0 + jj];
            Ks[(jj + 0) * KA_PAD + c] = v.x;
            Ks[(jj + 1) * KA_PAD + c] = v.y;
            Ks[(jj + 2) * KA_PAD + c] = v.z;
            Ks[(jj + 3) * KA_PAD + c] = v.w;
        }
        __syncthreads();

#pragma unroll 8
        for (int j = 0; j < TILE_N; j++) {
            const float* row = &Ks[j * KA_PAD];
            float4 a  = *(const float4*)&row[c0];
            float4 b0 = *(const float4*)&row[d0];
            float4 b1 = *(const float4*)&row[d0 + 4];
            float av[4] = {a.x, a.y, a.z, a.w};
            float bv[8] = {b0.x, b0.y, b0.z, b0.w, b1.x, b1.y, b1.z, b1.w};
#pragma unroll
            for (int i = 0; i < 4; i++)
#pragma unroll
                for (int q = 0; q < 8; q++) acc[i][q] += av[i] * bv[q];
        }
        __syncthreads();
    }

    float* gp = &g_Gpart[((size_t)s * BATCH + b) * CC * CC];
#pragma unroll
    for (int i = 0; i < 4; i++) {
        float4 o0 = make_float4(acc[i][0], acc[i][1], acc[i][2], acc[i][3]);
        float4 o1 = make_float4(acc[i][4], acc[i][5], acc[i][6], acc[i][7]);
        *(float4*)&gp[(c0 + i) * CC + d0 + 0] = o0;
        *(float4*)&gp[(c0 + i) * CC + d0 + 4] = o1;
    }
}

// ---------------------------------------------------------------------------
// Kernel B: reduce partials -> G, m3 = G*G, affinity = sigmoid(m3)
// grid = BATCH, block = 256. Deterministic reduction order.
// ---------------------------------------------------------------------------
__global__ __launch_bounds__(256) void affinity_kernel() {
    const int b = blockIdx.x;
    __shared__ float G[CC * CC];

    for (int e = threadIdx.x; e < CC * CC; e += 256) {
        float sum = 0.0f;
        for (int s = 0; s < SPLITS; s++)
            sum += g_Gpart[((size_t)s * BATCH + b) * CC * CC + e];
        G[e] = sum;
    }
    __syncthreads();

    for (int idx = threadIdx.x; idx < CC * CC; idx += 256) {
        int c = idx >> 6;
        int e = idx & 63;
        float m = 0.0f;
#pragma unroll 16
        for (int d = 0; d < CC; d++) m += G[c * CC + d] * G[d * CC + e];
        g_aff[b * CC * CC + idx] = 1.0f / (1.0f + expf(-m));
    }
}

// ---------------------------------------------------------------------------
// Kernel C: out[c,n] = gamma * sum_d aff[c,d]*K[d,n] + x[c,n]
// grid = (NN/TN, BATCH), block = 128. Thread tile 4(c) x 8(n).
// affinity is exactly symmetric, so Sa is read [d][c]-major via float4.
// The smem x-tile doubles as the residual source.
// ---------------------------------------------------------------------------
__global__ __launch_bounds__(128) void out_kernel(const float* __restrict__ x,
                                                  const float* __restrict__ gamma_p,
                                                  float* __restrict__ out) {
    const int n0 = blockIdx.x * TN;
    const int b  = blockIdx.y;
    const float* __restrict__ xb = x + (size_t)b * CC * NN;

    __shared__ float Kt[CC * TN];   // [d][n] 16 KB (natural layout, no transpose)
    __shared__ float Sa[CC * CC];   // affinity (symmetric) 16 KB

    const int tid = threadIdx.x;

#pragma unroll
    for (int r = 0; r < 8; r++) {
        int fi = (tid + r * 128) * 4;
        *(float4*)&Sa[fi] = *(const float4*)&g_aff[(size_t)b * CC * CC + fi];
    }
#pragma unroll
    for (int r = 0; r < 8; r++) {
        int fidx = tid + r * 128;
        int d  = fidx >> 4;          // 0..63
        int jj = (fidx & 15) * 4;    // 0..60
        *(float4*)&Kt[d * TN + jj] = *(const float4*)&xb[(size_t)d * NN + n0 + jj];
    }
    __syncthreads();

    const int tx = tid & 7;
    const int ty = tid >> 3;
    const int c0 = ty * 4;
    const int nn = tx * 8;

    float acc[4][8];
#pragma unroll
    for (int i = 0; i < 4; i++)
#pragma unroll
        for (int q = 0; q < 8; q++) acc[i][q] = 0.0f;

#pragma unroll 8
    for (int d = 0; d < CC; d++) {
        float4 a  = *(const float4*)&Sa[d * CC + c0];     // aff[c0..c0+3][d] by symmetry
        float4 b0 = *(const float4*)&Kt[d * TN + nn];
        float4 b1 = *(const float4*)&Kt[d * TN + nn + 4];
        float av[4] = {a.x, a.y, a.z, a.w};
        float bv[8] = {b0.x, b0.y, b0.z, b0.w, b1.x, b1.y, b1.z, b1.w};
#pragma unroll
        for (int i = 0; i < 4; i++)
#pragma unroll
            for (int q = 0; q < 8; q++) acc[i][q] += av[i] * bv[q];
    }

    const float g = *gamma_p;
    float* __restrict__ ob = out + (size_t)b * CC * NN;
#pragma unroll
    for (int i = 0; i < 4; i++) {
        const float* xt = &Kt[(c0 + i) * TN + nn];
        float4 o0 = make_float4(g * acc[i][0] + xt[0], g * acc[i][1] + xt[1],
                                g * acc[i][2] + xt[2], g * acc[i][3] + xt[3]);
        float4 o1 = make_float4(g * acc[i][4] + xt[4], g * acc[i][5] + xt[5],
                                g * acc[i][6] + xt[6], g * acc[i][7] + xt[7]);
        size_t base = (size_t)(c0 + i) * NN + n0 + nn;
        *(float4*)&ob[base + 0] = o0;
        *(float4*)&ob[base + 4] = o1;
    }
}

extern "C" void kernel_launch(void* const* d_in, const int* in_sizes, int n_in,
                              void* d_out, int out_size) {
    const float* x       = (const float*)d_in[0];
    const float* gamma_p = (const float*)d_in[1];
    float* out           = (float*)d_out;

    dim3 gridA(SPLITS, BATCH);
    gram_kernel<<<gridA, 128>>>(x);

    affinity_kernel<<<BATCH, 256>>>();

    dim3 gridC(NN / TN, BATCH);
    out_kernel<<<gridC, 128>>>(x, gamma_p, out);
}

// round 4
// speedup vs baseline: 2.6362x; 2.6362x over previous
#include <cuda_runtime.h>
#include <cuda_bf16.h>
#include <math.h>
#include <stdint.h>

#define BATCH 8
#define CC 64
#define NN 110592               // 48*48*48
#define CHUNK 2048
#define SPLITS 54               // 54*2048 = 110592
#define SROW 144                // bf16 smem row stride bytes (128B data + 16B pad)
#define XPAD 68                 // fp32 x-tile row stride (floats)

// Scratch (device globals; no allocation allowed)
__device__ float g_Gpart[SPLITS * BATCH * CC * CC];          // ~7.1 MB
__device__ __nv_bfloat16 g_aff_bf16[BATCH * CC * CC];        // 64 KB

// ---------------------------------------------------------------------------
// PTX helpers
// ---------------------------------------------------------------------------
__device__ __forceinline__ uint32_t s2u(const void* p) {
    uint32_t a;
    asm("{ .reg .u64 t; cvta.to.shared.u64 t, %1; cvt.u32.u64 %0, t; }"
        : "=r"(a) : "l"(p));
    return a;
}

__device__ __forceinline__ void ldsm4(uint32_t* r, uint32_t addr) {
    asm volatile("ldmatrix.sync.aligned.m8n8.x4.shared.b16 {%0,%1,%2,%3}, [%4];"
                 : "=r"(r[0]), "=r"(r[1]), "=r"(r[2]), "=r"(r[3]) : "r"(addr));
}

__device__ __forceinline__ void ldsm4t(uint32_t* r, uint32_t addr) {
    asm volatile("ldmatrix.sync.aligned.m8n8.x4.trans.shared.b16 {%0,%1,%2,%3}, [%4];"
                 : "=r"(r[0]), "=r"(r[1]), "=r"(r[2]), "=r"(r[3]) : "r"(addr));
}

__device__ __forceinline__ void mma_bf16(float* d, const uint32_t* a, const uint32_t* b) {
    asm volatile(
        "mma.sync.aligned.m16n8k16.row.col.f32.bf16.bf16.f32 "
        "{%0,%1,%2,%3}, {%4,%5,%6,%7}, {%8,%9}, {%0,%1,%2,%3};"
        : "+f"(d[0]), "+f"(d[1]), "+f"(d[2]), "+f"(d[3])
        : "r"(a[0]), "r"(a[1]), "r"(a[2]), "r"(a[3]), "r"(b[0]), "r"(b[1]));
}

__device__ __forceinline__ uint2 f4_to_bf(float4 v) {
    __nv_bfloat162 p0 = __float22bfloat162_rn(make_float2(v.x, v.y));
    __nv_bfloat162 p1 = __float22bfloat162_rn(make_float2(v.z, v.w));
    uint2 u;
    u.x = *(uint32_t*)&p0;
    u.y = *(uint32_t*)&p1;
    return u;
}

// ---------------------------------------------------------------------------
// Kernel A: partial Gram. G_s[c][d] = sum_{n in chunk s} K[c,n]K[d,n]
// grid = (SPLITS, BATCH), 128 threads (4 warps). bf16 MMA, fp32 accum.
// smem tile: K[64 c][64 n] as bf16, rows k(n)-contiguous, stride 144B.
// Warp w computes d-cols 16w..16w+15 for all 64 c-rows.
// ---------------------------------------------------------------------------
__global__ __launch_bounds__(128) void gram_kernel(const float* __restrict__ x) {
    const int s = blockIdx.x, b = blockIdx.y;
    const float* __restrict__ xb = x + (size_t)b * CC * NN + (size_t)s * CHUNK;

    __shared__ __align__(16) unsigned char kb[64 * SROW];

    const int tid = threadIdx.x;
    const int lane = tid & 31, w = tid >> 5;
    const int grp = lane >> 3, wi = lane & 7;
    const uint32_t kb0 = s2u(kb);
    // A frag tiles: grp0 (m0..7,k0) grp1 (m+8,k0) grp2 (m0..7,k+16B) grp3 (m+8,k+16B)
    const uint32_t aAddr = kb0 + (uint32_t)((wi + (grp & 1) * 8) * SROW + (grp >> 1) * 16);
    // B frag tiles: grp0 (d0..7,k0) grp1 (d0..7,k+16B) grp2 (d0+8..15,k0) grp3 (d0+8,k+16B)
    const uint32_t bAddr = kb0 + (uint32_t)((16 * w + wi + (grp >> 1) * 8) * SROW + (grp & 1) * 16);

    float acc[4][2][4];
#pragma unroll
    for (int mi = 0; mi < 4; mi++)
#pragma unroll
        for (int nj = 0; nj < 2; nj++)
#pragma unroll
            for (int q = 0; q < 4; q++) acc[mi][nj][q] = 0.0f;

    for (int t0 = 0; t0 < CHUNK; t0 += 64) {
#pragma unroll
        for (int i = 0; i < 8; i++) {
            int f = tid + 128 * i;
            int c = f >> 4, seg = f & 15;
            float4 v = *(const float4*)(xb + (size_t)c * NN + t0 + seg * 4);
            *(uint2*)(kb + c * SROW + seg * 8) = f4_to_bf(v);
        }
        __syncthreads();

#pragma unroll
        for (int ks = 0; ks < 4; ks++) {
            uint32_t bfr[4];
            ldsm4(bfr, bAddr + 32 * ks);
#pragma unroll
            for (int mi = 0; mi < 4; mi++) {
                uint32_t afr[4];
                ldsm4(afr, aAddr + mi * 16 * SROW + 32 * ks);
                mma_bf16(acc[mi][0], afr, bfr);
                mma_bf16(acc[mi][1], afr, bfr + 2);
            }
        }
        __syncthreads();
    }

    float* gp = g_Gpart + (size_t)(s * BATCH + b) * CC * CC;
    const int r0 = lane >> 2, cq = 2 * (lane & 3);
#pragma unroll
    for (int mi = 0; mi < 4; mi++)
#pragma unroll
        for (int nj = 0; nj < 2; nj++) {
            int col = 16 * w + 8 * nj + cq;
            int row = 16 * mi + r0;
            *(float2*)&gp[row * CC + col]      = make_float2(acc[mi][nj][0], acc[mi][nj][1]);
            *(float2*)&gp[(row + 8) * CC + col] = make_float2(acc[mi][nj][2], acc[mi][nj][3]);
        }
}

// ---------------------------------------------------------------------------
// Kernel B: reduce partials -> G, m3 = G*G, affinity = sigmoid(m3) -> bf16
// grid = BATCH, block = 256. Deterministic reduction order.
// ---------------------------------------------------------------------------
__global__ __launch_bounds__(256) void affinity_kernel() {
    const int b = blockIdx.x;
    __shared__ float G[CC * CC];

    for (int e = threadIdx.x; e < CC * CC; e += 256) {
        float sum = 0.0f;
        for (int s = 0; s < SPLITS; s++)
            sum += g_Gpart[(size_t)(s * BATCH + b) * CC * CC + e];
        G[e] = sum;
    }
    __syncthreads();

    for (int idx = threadIdx.x; idx < CC * CC; idx += 256) {
        int c = idx >> 6;
        int e = idx & 63;
        float m = 0.0f;
#pragma unroll 16
        for (int d = 0; d < CC; d++) m += G[c * CC + d] * G[d * CC + e];
        float sig = 1.0f / (1.0f + expf(-m));
        g_aff_bf16[b * CC * CC + idx] = __float2bfloat16(sig);
    }
}

// ---------------------------------------------------------------------------
// Kernel C: out[c,n] = gamma * sum_d aff[c,d]*K[d,n] + x[c,n]
// grid = (NN/64, BATCH), 128 threads (4 warps). bf16 MMA, fp32 residual.
// smem: aff [c][d] bf16 (A, no-trans ldmatrix), x tile [d][n] bf16 (B via
// trans ldmatrix, k = d rows), x tile [c][n] fp32 (residual).
// Warp w computes n-cols 16w..16w+15 for all 64 c-rows.
// ---------------------------------------------------------------------------
__global__ __launch_bounds__(128) void out_kernel(const float* __restrict__ x,
                                                  const float* __restrict__ gamma_p,
                                                  float* __restrict__ out) {
    const int nb = blockIdx.x, b = blockIdx.y;
    const float* __restrict__ xb = x + (size_t)b * CC * NN + (size_t)nb * 64;
    float* __restrict__ ob = out + (size_t)b * CC * NN + (size_t)nb * 64;

    __shared__ __align__(16) float x_s[64 * XPAD];
    __shared__ __align__(16) unsigned char kb[64 * SROW];
    __shared__ __align__(16) unsigned char ab[64 * SROW];

    const int tid = threadIdx.x;
    const int lane = tid & 31, w = tid >> 5;

    // load affinity (bf16) into padded smem
    const __nv_bfloat16* affb = g_aff_bf16 + (size_t)b * CC * CC;
#pragma unroll
    for (int i = 0; i < 4; i++) {
        int f = tid + 128 * i;
        int r = f >> 3, sg = f & 7;
        *(uint4*)(ab + r * SROW + sg * 16) = *(const uint4*)(affb + r * CC + sg * 8);
    }
    // load x tile: fp32 copy + bf16 copy
#pragma unroll
    for (int i = 0; i < 8; i++) {
        int f = tid + 128 * i;
        int d = f >> 4, seg = f & 15;
        float4 v = *(const float4*)(xb + (size_t)d * NN + seg * 4);
        *(float4*)&x_s[d * XPAD + seg * 4] = v;
        *(uint2*)(kb + d * SROW + seg * 8) = f4_to_bf(v);
    }
    __syncthreads();

    const int grp = lane >> 3, wi = lane & 7;
    const uint32_t ab0 = s2u(ab), kb0 = s2u(kb);
    // A = aff, row-major [c][d]: same grouping as gram A
    const uint32_t aAddr = ab0 + (uint32_t)((wi + (grp & 1) * 8) * SROW + (grp >> 1) * 16);
    // B via trans: tiles grp0 (k0..7, col 32w) grp1 (k8..15, col 32w)
    //              grp2 (k0..7, col 32w+16) grp3 (k8..15, col 32w+16)
    const uint32_t bAddr = kb0 + (uint32_t)((wi + (grp & 1) * 8) * SROW + 32 * w + (grp >> 1) * 16);

    float acc[4][2][4];
#pragma unroll
    for (int mi = 0; mi < 4; mi++)
#pragma unroll
        for (int nj = 0; nj < 2; nj++)
#pragma unroll
            for (int q = 0; q < 4; q++) acc[mi][nj][q] = 0.0f;

#pragma unroll
    for (int ks = 0; ks < 4; ks++) {
        uint32_t bfr[4];
        ldsm4t(bfr, bAddr + ks * 16 * SROW);
#pragma unroll
        for (int mi = 0; mi < 4; mi++) {
            uint32_t afr[4];
            ldsm4(afr, aAddr + mi * 16 * SROW + 32 * ks);
            mma_bf16(acc[mi][0], afr, bfr);
            mma_bf16(acc[mi][1], afr, bfr + 2);
        }
    }

    const float g = *gamma_p;
    const int r0 = lane >> 2, cq = 2 * (lane & 3);
#pragma unroll
    for (int mi = 0; mi < 4; mi++)
#pragma unroll
        for (int nj = 0; nj < 2; nj++) {
            int nl = 16 * w + 8 * nj + cq;
            int c = 16 * mi + r0;
            float2 o0 = make_float2(g * acc[mi][nj][0] + x_s[c * XPAD + nl],
                                    g * acc[mi][nj][1] + x_s[c * XPAD + nl + 1]);
            float2 o1 = make_float2(g * acc[mi][nj][2] + x_s[(c + 8) * XPAD + nl],
                                    g * acc[mi][nj][3] + x_s[(c + 8) * XPAD + nl + 1]);
            *(float2*)(ob + (size_t)c * NN + nl) = o0;
            *(float2*)(ob + (size_t)(c + 8) * NN + nl) = o1;
        }
}

extern "C" void kernel_launch(void* const* d_in, const int* in_sizes, int n_in,
                              void* d_out, int out_size) {
    const float* x       = (const float*)d_in[0];
    const float* gamma_p = (const float*)d_in[1];
    float* out           = (float*)d_out;

    dim3 gridA(SPLITS, BATCH);
    gram_kernel<<<gridA, 128>>>(x);

    affinity_kernel<<<BATCH, 256>>>();

    dim3 gridC(NN / 64, BATCH);
    out_kernel<<<gridC, 128>>>(x, gamma_p, out);
}

// round 8
// speedup vs baseline: 3.2333x; 1.2265x over previous
#include <cuda_runtime.h>
#include <cuda_bf16.h>
#include <math.h>
#include <stdint.h>

#define BATCH 8
#define CC 64
#define NN 110592               // 48*48*48
#define SPLITS 36
#define CHUNK 3072              // 36*3072 = 110592
#define TILE 128                // n per pipeline step
#define NSTEP (CHUNK / TILE)    // 24
#define SROW 144                // 64-col bf16 row stride bytes (128B + 16B pad)
#define SROW2 272               // 128-col bf16 row stride bytes (256B + 16B pad)

// Scratch (device globals; no allocation allowed)
__device__ float g_Gpart[SPLITS * BATCH * CC * CC];          // ~4.7 MB
__device__ __nv_bfloat16 g_aff_bf16[BATCH * CC * CC];        // 64 KB

// ---------------------------------------------------------------------------
// PTX helpers
// ---------------------------------------------------------------------------
__device__ __forceinline__ uint32_t s2u(const void* p) {
    uint32_t a;
    asm("{ .reg .u64 t; cvta.to.shared.u64 t, %1; cvt.u32.u64 %0, t; }"
        : "=r"(a) : "l"(p));
    return a;
}

__device__ __forceinline__ void ldsm4(uint32_t* r, uint32_t addr) {
    asm volatile("ldmatrix.sync.aligned.m8n8.x4.shared.b16 {%0,%1,%2,%3}, [%4];"
                 : "=r"(r[0]), "=r"(r[1]), "=r"(r[2]), "=r"(r[3]) : "r"(addr));
}

__device__ __forceinline__ void ldsm4t(uint32_t* r, uint32_t addr) {
    asm volatile("ldmatrix.sync.aligned.m8n8.x4.trans.shared.b16 {%0,%1,%2,%3}, [%4];"
                 : "=r"(r[0]), "=r"(r[1]), "=r"(r[2]), "=r"(r[3]) : "r"(addr));
}

__device__ __forceinline__ void mma_bf16(float* d, const uint32_t* a, const uint32_t* b) {
    asm volatile(
        "mma.sync.aligned.m16n8k16.row.col.f32.bf16.bf16.f32 "
        "{%0,%1,%2,%3}, {%4,%5,%6,%7}, {%8,%9}, {%0,%1,%2,%3};"
        : "+f"(d[0]), "+f"(d[1]), "+f"(d[2]), "+f"(d[3])
        : "r"(a[0]), "r"(a[1]), "r"(a[2]), "r"(a[3]), "r"(b[0]), "r"(b[1]));
}

__device__ __forceinline__ uint2 f4_to_bf(float4 v) {
    __nv_bfloat162 p0 = __float22bfloat162_rn(make_float2(v.x, v.y));
    __nv_bfloat162 p1 = __float22bfloat162_rn(make_float2(v.z, v.w));
    uint2 u;
    u.x = *(uint32_t*)&p0;
    u.y = *(uint32_t*)&p1;
    return u;
}

// ---------------------------------------------------------------------------
// Kernel A: partial Gram. G_s[c][d] = sum_{n in chunk s} K[c,n]K[d,n]
// grid = (36, 8) = 288 CTAs (~2/SM), 256 threads (8 warps).
// 128-wide n tiles, register-prefetch double buffering, bf16 MMA / fp32 acc.
// Warp w computes d-cols 8w..8w+7 for all 64 c-rows.
// ---------------------------------------------------------------------------
__global__ __launch_bounds__(256) void gram_kernel(const float* __restrict__ x) {
    const int s = blockIdx.x, b = blockIdx.y;
    const float* __restrict__ xb = x + (size_t)b * CC * NN + (size_t)s * CHUNK;

    __shared__ __align__(16) unsigned char kb[2][64 * SROW2];

    const int tid = threadIdx.x;
    const int lane = tid & 31, w = tid >> 5;
    const int grp = lane >> 3, wi = lane & 7;

    const uint32_t k0 = s2u(kb[0]);
    const uint32_t bufstep = 64 * SROW2;
    // A frag (16m x 16k per ldsm4): g0 (m0..7,k0) g1 (m8..15,k0) g2 (m0..7,+16B) g3 (m8..15,+16B)
    const uint32_t aAddr = k0 + (uint32_t)((wi + (grp & 1) * 8) * SROW2 + (grp >> 1) * 16);
    // B frag (8d x 32k per ldsm4): tile g = rows 8w+wi, byte col g*16
    const uint32_t bAddr = k0 + (uint32_t)((8 * w + wi) * SROW2 + grp * 16);

    float acc[4][4];
#pragma unroll
    for (int mi = 0; mi < 4; mi++)
#pragma unroll
        for (int q = 0; q < 4; q++) acc[mi][q] = 0.0f;

    // thread loads rows c = w + 8i, cols lane*4..lane*4+3 (512B/warp contiguous)
    float4 v[8];
#pragma unroll
    for (int i = 0; i < 8; i++)
        v[i] = *(const float4*)(xb + (size_t)(w + 8 * i) * NN + lane * 4);
#pragma unroll
    for (int i = 0; i < 8; i++)
        *(uint2*)(kb[0] + (w + 8 * i) * SROW2 + lane * 8) = f4_to_bf(v[i]);
    __syncthreads();

    for (int t = 0; t < NSTEP; t++) {
        const uint32_t cur = (t & 1) * bufstep;
        if (t + 1 < NSTEP) {
            const float* src = xb + (size_t)(t + 1) * TILE;
#pragma unroll
            for (int i = 0; i < 8; i++)
                v[i] = *(const float4*)(src + (size_t)(w + 8 * i) * NN + lane * 4);
        }
#pragma unroll
        for (int kd = 0; kd < 4; kd++) {
            uint32_t bfr[4];
            ldsm4(bfr, bAddr + cur + kd * 64);
#pragma unroll
            for (int mi = 0; mi < 4; mi++) {
                uint32_t a0[4], a1[4];
                ldsm4(a0, aAddr + cur + mi * 16 * SROW2 + kd * 64);
                ldsm4(a1, aAddr + cur + mi * 16 * SROW2 + kd * 64 + 32);
                mma_bf16(acc[mi], a0, bfr);
                mma_bf16(acc[mi], a1, bfr + 2);
            }
        }
        if (t + 1 < NSTEP) {
            unsigned char* dst = kb[(t + 1) & 1];
#pragma unroll
            for (int i = 0; i < 8; i++)
                *(uint2*)(dst + (w + 8 * i) * SROW2 + lane * 8) = f4_to_bf(v[i]);
            __syncthreads();
        }
    }

    float* gp = g_Gpart + (size_t)(s * BATCH + b) * CC * CC;
    const int r0 = lane >> 2, cq = 2 * (lane & 3);
#pragma unroll
    for (int mi = 0; mi < 4; mi++) {
        int col = 8 * w + cq;
        *(float2*)&gp[(16 * mi + r0) * CC + col]     = make_float2(acc[mi][0], acc[mi][1]);
        *(float2*)&gp[(16 * mi + r0 + 8) * CC + col] = make_float2(acc[mi][2], acc[mi][3]);
    }
}

// ---------------------------------------------------------------------------
// Kernel B: reduce partials -> G, m3 = G*G, affinity = sigmoid(m3) -> bf16
// ---------------------------------------------------------------------------
__global__ __launch_bounds__(256) void affinity_kernel() {
    const int b = blockIdx.x;
    __shared__ float G[CC * CC];

    for (int e = threadIdx.x; e < CC * CC; e += 256) {
        float sum = 0.0f;
        for (int s = 0; s < SPLITS; s++)
            sum += g_Gpart[(size_t)(s * BATCH + b) * CC * CC + e];
        G[e] = sum;
    }
    __syncthreads();

    for (int idx = threadIdx.x; idx < CC * CC; idx += 256) {
        int c = idx >> 6;
        int e = idx & 63;
        float m = 0.0f;
#pragma unroll 16
        for (int d = 0; d < CC; d++) m += G[c * CC + d] * G[d * CC + e];
        float sig = 1.0f / (1.0f + expf(-m));
        g_aff_bf16[b * CC * CC + idx] = __float2bfloat16(sig);
    }
}

// ---------------------------------------------------------------------------
// Kernel C: out[c,n] = gamma * sum_d aff[c,d]*K[d,n] + x[c,n]
// grid = (NN/128, BATCH) = 6912 CTAs, 256 threads (8 warps).
// Warp w computes n-cols 16w..16w+15 for all 64 c-rows. Residual x reread
// from gmem at output positions (L2-hot: tile just loaded).
// ---------------------------------------------------------------------------
__global__ __launch_bounds__(256) void out_kernel(const float* __restrict__ x,
                                                  const float* __restrict__ gamma_p,
                                                  float* __restrict__ out) {
    const int nb = blockIdx.x, b = blockIdx.y;
    const float* __restrict__ xb = x + (size_t)b * CC * NN + (size_t)nb * TILE;
    float* __restrict__ ob = out + (size_t)b * CC * NN + (size_t)nb * TILE;

    __shared__ __align__(16) unsigned char kb[64 * SROW2];   // x tile bf16 [d][n]
    __shared__ __align__(16) unsigned char ab[64 * SROW];    // affinity bf16 [c][d]

    const int tid = threadIdx.x;
    const int lane = tid & 31, w = tid >> 5;

    const __nv_bfloat16* affb = g_aff_bf16 + (size_t)b * CC * CC;
#pragma unroll
    for (int i = 0; i < 2; i++) {
        int f = tid + 256 * i;
        int r = f >> 3, sg = f & 7;
        *(uint4*)(ab + r * SROW + sg * 16) = *(const uint4*)(affb + r * CC + sg * 8);
    }
#pragma unroll
    for (int i = 0; i < 8; i++) {
        float4 v = *(const float4*)(xb + (size_t)(w + 8 * i) * NN + lane * 4);
        *(uint2*)(kb + (w + 8 * i) * SROW2 + lane * 8) = f4_to_bf(v);
    }
    __syncthreads();

    const int grp = lane >> 3, wi = lane & 7;
    const uint32_t ab0 = s2u(ab), kb0 = s2u(kb);
    // A = aff [c][d] row-major
    const uint32_t aAddr = ab0 + (uint32_t)((wi + (grp & 1) * 8) * SROW + (grp >> 1) * 16);
    // B via trans ldmatrix: 16x16 tiles at rows k(d), cols 16w..16w+15
    const uint32_t bAddr = kb0 + (uint32_t)((wi + (grp & 1) * 8) * SROW2 + 32 * w + (grp >> 1) * 16);

    float acc[4][2][4];
#pragma unroll
    for (int mi = 0; mi < 4; mi++)
#pragma unroll
        for (int nj = 0; nj < 2; nj++)
#pragma unroll
            for (int q = 0; q < 4; q++) acc[mi][nj][q] = 0.0f;

#pragma unroll
    for (int ks = 0; ks < 4; ks++) {
        uint32_t bfr[4];
        ldsm4t(bfr, bAddr + ks * 16 * SROW2);
#pragma unroll
        for (int mi = 0; mi < 4; mi++) {
            uint32_t afr[4];
            ldsm4(afr, aAddr + mi * 16 * SROW + 32 * ks);
            mma_bf16(acc[mi][0], afr, bfr);
            mma_bf16(acc[mi][1], afr, bfr + 2);
        }
    }

    const float g = *gamma_p;
    const int r0 = lane >> 2, cq = 2 * (lane & 3);
#pragma unroll
    for (int mi = 0; mi < 4; mi++)
#pragma unroll
        for (int nj = 0; nj < 2; nj++) {
            int nl = 16 * w + 8 * nj + cq;
            int c = 16 * mi + r0;
            size_t i0 = (size_t)c * NN + nl;
            size_t i1 = (size_t)(c + 8) * NN + nl;
            float2 x0 = *(const float2*)(xb + i0);   // L2 hit
            float2 x1 = *(const float2*)(xb + i1);
            *(float2*)(ob + i0) = make_float2(g * acc[mi][nj][0] + x0.x,
                                              g * acc[mi][nj][1] + x0.y);
            *(float2*)(ob + i1) = make_float2(g * acc[mi][nj][2] + x1.x,
                                              g * acc[mi][nj][3] + x1.y);
        }
}

extern "C" void kernel_launch(void* const* d_in, const int* in_sizes, int n_in,
                              void* d_out, int out_size) {
    const float* x       = (const float*)d_in[0];
    const float* gamma_p = (const float*)d_in[1];
    float* out           = (float*)d_out;

    dim3 gridA(SPLITS, BATCH);
    gram_kernel<<<gridA, 256>>>(x);

    affinity_kernel<<<BATCH, 256>>>();

    dim3 gridC(NN / TILE, BATCH);
    out_kernel<<<gridC, 256>>>(x, gamma_p, out);
}